// round 12
// baseline (speedup 1.0000x reference)
#include <cuda_runtime.h>
#include <cuda_bf16.h>
#include <cstdint>

namespace {

constexpr int SQn = 2048, SKn = 2048, Dn = 128;
constexpr float SCALE = 22.62741699796952f; // 2*sqrt(128)

constexpr int STRIDE_W = 68;             // words per padded smem row (128 bf16 + 16B pad)
constexpr int STRIDE_B = STRIDE_W * 4;   // 272 B
constexpr int CHUNK_ROWS = 32;           // keys per pipeline chunk
constexpr int BUF_B   = CHUNK_ROWS * STRIDE_B;  // 8704 B (one of KH,KL,VH,VL)
constexpr int STAGE_B = 4 * BUF_B;              // 34816 B per stage
constexpr int NSTAGE  = 6;
constexpr int SMEM_TOTAL = NSTAGE * STAGE_B;    // 208896 B
constexpr int NCHUNK = SKn / CHUNK_ROWS;        // 64

// scratch (R10 layout): [bh(32)][chunk64(32)][buf: KH,KL,VH,VL (17408 B each)]
constexpr int NCH64   = 32;
constexpr int BUF64_B = 64 * STRIDE_B;          // 17408
constexpr int SCH64_B = 4 * BUF64_B;            // 69632
__device__ __align__(16) char g_scratch[32ull * NCH64 * SCH64_B];

__device__ __forceinline__ uint32_t packbf(float a, float b) {
    __nv_bfloat162 t = __floats2bfloat162_rn(a, b);
    return *reinterpret_cast<uint32_t*>(&t);
}
__device__ __forceinline__ uint32_t prmt_hi(uint32_t a, uint32_t b) {
    uint32_t d; asm("prmt.b32 %0,%1,%2,0x7632;" : "=r"(d) : "r"(a), "r"(b)); return d;
}
__device__ __forceinline__ float truncbf(float x) {
    return __uint_as_float(__float_as_uint(x) & 0xFFFF0000u);
}
__device__ __forceinline__ void mma16816(float* d, const uint32_t* a, uint32_t b0, uint32_t b1) {
    asm volatile(
        "mma.sync.aligned.m16n8k16.row.col.f32.bf16.bf16.f32 "
        "{%0,%1,%2,%3}, {%4,%5,%6,%7}, {%8,%9}, {%0,%1,%2,%3};\n"
        : "+f"(d[0]), "+f"(d[1]), "+f"(d[2]), "+f"(d[3])
        : "r"(a[0]), "r"(a[1]), "r"(a[2]), "r"(a[3]), "r"(b0), "r"(b1));
}
__device__ __forceinline__ void ldsm4(uint32_t* r, uint32_t saddr) {
    asm volatile("ldmatrix.sync.aligned.m8n8.x4.shared.b16 {%0,%1,%2,%3}, [%4];\n"
                 : "=r"(r[0]), "=r"(r[1]), "=r"(r[2]), "=r"(r[3]) : "r"(saddr));
}
__device__ __forceinline__ void ldsm4t(uint32_t* r, uint32_t saddr) {
    asm volatile("ldmatrix.sync.aligned.m8n8.x4.trans.shared.b16 {%0,%1,%2,%3}, [%4];\n"
                 : "=r"(r[0]), "=r"(r[1]), "=r"(r[2]), "=r"(r[3]) : "r"(saddr));
}
__device__ __forceinline__ void cp16(uint32_t sdst, const void* gsrc) {
    asm volatile("cp.async.cg.shared.global [%0], [%1], 16;" :: "r"(sdst), "l"(gsrc) : "memory");
}
#define CP_COMMIT() asm volatile("cp.async.commit_group;" ::: "memory")
#define CP_WAIT(n)  asm volatile("cp.async.wait_group %0;" :: "n"(n) : "memory")

__device__ __forceinline__ void bar_syncg(int id) {
    asm volatile("bar.sync %0, 128;" :: "r"(id) : "memory");
}
__device__ __forceinline__ void bar_arriveg(int id) {
    asm volatile("bar.arrive %0, 128;" :: "r"(id) : "memory");
}

// ---------------- pre-pass: K,V fp32 -> hi/lo bf16 scratch (padded rows) ----------------
__global__ __launch_bounds__(256) void prepass(const float* __restrict__ K,
                                               const float* __restrict__ V) {
    uint32_t g = blockIdx.x * 256u + threadIdx.x;   // 0 .. 4194303
    int c4 = g & 31;                 // float4 within row
    int r  = (g >> 5) & 2047;        // key row
    int bh = (g >> 16) & 31;
    int tv = g >> 21;                // 0 = K, 1 = V
    const float* src = (tv ? V : K) + (((size_t)bh * SKn + r) * Dn + c4 * 4);
    float4 f = *reinterpret_cast<const float4*>(src);
    uint32_t bx = __float_as_uint(f.x), by = __float_as_uint(f.y);
    uint32_t bz = __float_as_uint(f.z), bw = __float_as_uint(f.w);
    uint2 hi = make_uint2(prmt_hi(bx, by), prmt_hi(bz, bw));
    uint2 lo = make_uint2(packbf(f.x - truncbf(f.x), f.y - truncbf(f.y)),
                          packbf(f.z - truncbf(f.z), f.w - truncbf(f.w)));
    char* base = g_scratch
        + (((size_t)bh * NCH64 + (r >> 6)) * 4 + (tv ? 2 : 0)) * (size_t)BUF64_B
        + (r & 63) * STRIDE_B + c4 * 8;
    *reinterpret_cast<uint2*>(base)           = hi;
    *reinterpret_cast<uint2*>(base + BUF64_B) = lo;
}

// ---------------- main kernel: 128 q-rows, 256 thr, 4 ping-pong groups ----------------
__global__ __launch_bounds__(256, 1) void attn_kernel(
    const float* __restrict__ Q, const int* __restrict__ M, float* __restrict__ O)
{
    extern __shared__ char smem[];
    const uint32_t sb = (uint32_t)__cvta_generic_to_shared(smem);

    // Q (hi/lo) overlays stages 0+1: 2 x 128 rows x 272 B = 69632 B
    uint32_t* Qh = reinterpret_cast<uint32_t*>(smem);
    uint32_t* Ql = reinterpret_cast<uint32_t*>(smem + 128 * STRIDE_B);
    const uint32_t sQh = sb, sQl = sb + 128 * STRIDE_B;

    const int tid  = threadIdx.x;
    const int warp = tid >> 5, lane = tid & 31;
    const int gid  = lane >> 2, qid = lane & 3;
    const int qr   = warp * 16;
    const int grp  = warp >> 1;   // groups of 2 warps; g0 = producer + lead

    const int bh = blockIdx.y;
    const int qt = blockIdx.x;

    const float* Qg = Q + ((size_t)bh * SQn + (size_t)qt * 128) * Dn;
    const int*   Mg = M + ((size_t)bh * SQn + (size_t)qt * 128) * SKn;
    float*       Og = O + ((size_t)bh * SQn + (size_t)qt * 128) * Dn;
    const char*  Sg = g_scratch + (size_t)bh * NCH64 * SCH64_B;

    // lane-derived ldmatrix offsets (bytes)
    const uint32_t bkOff = ((lane & 7) + ((lane >> 4) & 1) * 8) * STRIDE_B + ((lane >> 3) & 1) * 16;
    const uint32_t vOff  = ((lane & 7) + ((lane >> 3) & 1) * 8) * STRIDE_B + ((lane >> 4) & 1) * 16;
    const uint32_t qOff  = (qr + (lane & 15)) * STRIDE_B + ((lane >> 4) & 1) * 16;

    // ---- Q tile: global -> smem (hi/lo) ----
    {
        const float4* src = reinterpret_cast<const float4*>(Qg);
        #pragma unroll
        for (int it = 0; it < 16; ++it) {
            int idx = tid + it * 256;
            int row = idx >> 5, c4 = idx & 31;
            float4 v = src[idx];
            uint32_t bx = __float_as_uint(v.x), by = __float_as_uint(v.y);
            uint32_t bz = __float_as_uint(v.z), bw = __float_as_uint(v.w);
            int off = row * STRIDE_W + c4 * 2;
            *reinterpret_cast<uint2*>(Qh + off) = make_uint2(prmt_hi(bx, by), prmt_hi(bz, bw));
            *reinterpret_cast<uint2*>(Ql + off) =
                make_uint2(packbf(v.x - truncbf(v.x), v.y - truncbf(v.y)),
                           packbf(v.z - truncbf(v.z), v.w - truncbf(v.w)));
        }
    }
    __syncthreads();

    // ---- hoist Q fragments (invariant across chunks) ----
    uint32_t qfh[8][4], qfl[8][4];
    #pragma unroll
    for (int ds = 0; ds < 8; ++ds) {
        ldsm4(qfh[ds], sQh + qOff + ds * 32);
        ldsm4(qfl[ds], sQl + qOff + ds * 32);
    }
    __syncthreads();   // Q reads done before stages 0,1 are overwritten

    // ---- g0 prologue: issue chunks 0,1,2 into stages 0,1,2 ----
    if (grp == 0) {
        #pragma unroll
        for (int n = 0; n < 3; ++n) {
            const char* gb = Sg + (size_t)(n >> 1) * SCH64_B + (size_t)(n & 1) * BUF_B;
            const uint32_t sn = sb + n * STAGE_B;
            #pragma unroll 2
            for (int i = 0; i < 34; ++i) {
                int idx = i * 64 + tid;            // tid < 64 in grp 0; 0..2175
                int buf = idx / 544, rem = idx - buf * 544;
                cp16(sn + buf * BUF_B + rem * 16, gb + buf * BUF64_B + rem * 16);
            }
            CP_COMMIT();
        }
    }

    float o[16][4];
    #pragma unroll
    for (int i = 0; i < 16; ++i)
        #pragma unroll
        for (int j = 0; j < 4; ++j) o[i][j] = 0.f;

    #pragma unroll 1
    for (int c = 0; c < NCHUNK; ++c) {
        const int st_i = c - (c / NSTAGE) * NSTAGE;     // c % 6

        // ---- acquire chunk c ----
        if (grp == 0) {
            CP_WAIT(2);                         // pending {c+1,c+2}; chunk c complete
        } else {
            bar_syncg(1 + (grp - 1) * 4 + (c & 3));   // F(grp-1): predecessor done chunk c
        }

        const uint32_t st = sb + st_i * STAGE_B;
        const uint32_t sKH = st, sKL = st + BUF_B, sVH = st + 2 * BUF_B, sVL = st + 3 * BUF_B;

        // mask prefetch (32 keys)
        const int* m0 = Mg + (size_t)(qr + gid) * SKn + c * CHUNK_ROWS + qid * 2;
        const int* m1 = m0 + 8 * (size_t)SKn;
        int2 ma[4], mb[4];
        #pragma unroll
        for (int j = 0; j < 4; ++j) {
            ma[j] = *reinterpret_cast<const int2*>(m0 + j * 8);
            mb[j] = *reinterpret_cast<const int2*>(m1 + j * 8);
        }

        // ---- GEMM1: S[16q x 32k] = Q·K^T (bf16x3) ----
        float s[4][4];
        #pragma unroll
        for (int j = 0; j < 4; ++j) { s[j][0]=0.f; s[j][1]=0.f; s[j][2]=0.f; s[j][3]=0.f; }

        #pragma unroll
        for (int ds = 0; ds < 8; ++ds) {
            uint32_t bh0[4], bh1[4], bl0[4], bl1[4];
            const uint32_t kcol = bkOff + ds * 32;
            ldsm4(bh0, sKH + kcol);
            ldsm4(bh1, sKH + 16 * STRIDE_B + kcol);
            ldsm4(bl0, sKL + kcol);
            ldsm4(bl1, sKL + 16 * STRIDE_B + kcol);
            mma16816(s[0], qfh[ds], bh0[0], bh0[1]);
            mma16816(s[1], qfh[ds], bh0[2], bh0[3]);
            mma16816(s[2], qfh[ds], bh1[0], bh1[1]);
            mma16816(s[3], qfh[ds], bh1[2], bh1[3]);
            mma16816(s[0], qfl[ds], bh0[0], bh0[1]);
            mma16816(s[1], qfl[ds], bh0[2], bh0[3]);
            mma16816(s[2], qfl[ds], bh1[0], bh1[1]);
            mma16816(s[3], qfl[ds], bh1[2], bh1[3]);
            mma16816(s[0], qfh[ds], bl0[0], bl0[1]);
            mma16816(s[1], qfh[ds], bl0[2], bl0[3]);
            mma16816(s[2], qfh[ds], bl1[0], bl1[1]);
            mma16816(s[3], qfh[ds], bl1[2], bl1[3]);
        }

        // ---- mask + scale -> P ----
        float p[4][4];
        #pragma unroll
        for (int j = 0; j < 4; ++j) {
            p[j][0] = ma[j].x ? s[j][0] * SCALE : 0.f;
            p[j][1] = ma[j].y ? s[j][1] * SCALE : 0.f;
            p[j][2] = mb[j].x ? s[j][2] * SCALE : 0.f;
            p[j][3] = mb[j].y ? s[j][3] * SCALE : 0.f;
        }

        // ---- GEMM2: O += P[16x32]·V[32x128], paired d-tiles ----
        #pragma unroll
        for (int kk = 0; kk < 2; ++kk) {
            uint32_t ahi[4], alo[4];
            {
                const float* p0 = p[kk*2 + 0];
                const float* p1 = p[kk*2 + 1];
                ahi[0] = prmt_hi(__float_as_uint(p0[0]), __float_as_uint(p0[1]));
                ahi[1] = prmt_hi(__float_as_uint(p0[2]), __float_as_uint(p0[3]));
                ahi[2] = prmt_hi(__float_as_uint(p1[0]), __float_as_uint(p1[1]));
                ahi[3] = prmt_hi(__float_as_uint(p1[2]), __float_as_uint(p1[3]));
                alo[0] = packbf(p0[0] - truncbf(p0[0]), p0[1] - truncbf(p0[1]));
                alo[1] = packbf(p0[2] - truncbf(p0[2]), p0[3] - truncbf(p0[3]));
                alo[2] = packbf(p1[0] - truncbf(p1[0]), p1[1] - truncbf(p1[1]));
                alo[3] = packbf(p1[2] - truncbf(p1[2]), p1[3] - truncbf(p1[3]));
            }
            const uint32_t vbase = (uint32_t)(kk * 16) * STRIDE_B + vOff;

            #pragma unroll
            for (int tp = 0; tp < 4; ++tp) {
                uint32_t vh0[4], vl0[4], vh1[4], vl1[4];
                ldsm4t(vh0, sVH + vbase + (2*tp    ) * 32);
                ldsm4t(vl0, sVL + vbase + (2*tp    ) * 32);
                ldsm4t(vh1, sVH + vbase + (2*tp + 1) * 32);
                ldsm4t(vl1, sVL + vbase + (2*tp + 1) * 32);
                float* o0 = o[4*tp + 0];
                float* o1 = o[4*tp + 1];
                float* o2 = o[4*tp + 2];
                float* o3 = o[4*tp + 3];
                mma16816(o0, ahi, vh0[0], vh0[1]);
                mma16816(o1, ahi, vh0[2], vh0[3]);
                mma16816(o2, ahi, vh1[0], vh1[1]);
                mma16816(o3, ahi, vh1[2], vh1[3]);
                mma16816(o0, alo, vh0[0], vh0[1]);
                mma16816(o1, alo, vh0[2], vh0[3]);
                mma16816(o2, alo, vh1[0], vh1[1]);
                mma16816(o3, alo, vh1[2], vh1[3]);
                mma16816(o0, ahi, vl0[0], vl0[1]);
                mma16816(o1, ahi, vl0[2], vl0[3]);
                mma16816(o2, ahi, vl1[0], vl1[1]);
                mma16816(o3, ahi, vl1[2], vl1[3]);
            }
        }

        // ---- release / refill ----
        if (grp < 3) bar_arriveg(1 + grp * 4 + (c & 3));   // F(grp): successor may start c
        if (grp == 0) {
            const int n = c + 3;
            if (n < NCHUNK) {
                if (c >= 3) bar_syncg(13 + (c % 3));       // E: g3 finished chunk c-3
                const char* gb = Sg + (size_t)(n >> 1) * SCH64_B + (size_t)(n & 1) * BUF_B;
                const uint32_t sn = sb + (n - (n / NSTAGE) * NSTAGE) * STAGE_B;
                #pragma unroll 2
                for (int i = 0; i < 34; ++i) {
                    int idx = i * 64 + tid;
                    int buf = idx / 544, rem = idx - buf * 544;
                    cp16(sn + buf * BUF_B + rem * 16, gb + buf * BUF64_B + rem * 16);
                }
            }
            CP_COMMIT();   // uniform commit count
        } else if (grp == 3) {
            bar_arriveg(13 + (c % 3));                     // E: g3 done with chunk c
        }
    }

    // ---- epilogue ----
    float* o0 = Og + (size_t)(qr + gid) * Dn + qid * 2;
    float* o1 = o0 + 8 * Dn;
    #pragma unroll
    for (int nd = 0; nd < 16; ++nd) {
        *reinterpret_cast<float2*>(o0 + nd * 8) = make_float2(o[nd][0], o[nd][1]);
        *reinterpret_cast<float2*>(o1 + nd * 8) = make_float2(o[nd][2], o[nd][3]);
    }
}

} // namespace

extern "C" void kernel_launch(void* const* d_in, const int* in_sizes, int n_in,
                              void* d_out, int out_size) {
    (void)in_sizes; (void)n_in; (void)out_size;
    const float* Q = (const float*)d_in[0];
    const float* K = (const float*)d_in[1];
    const float* V = (const float*)d_in[2];
    const int*   M = (const int*)d_in[3];
    float*       O = (float*)d_out;

    prepass<<<16384, 256>>>(K, V);

    cudaFuncSetAttribute(attn_kernel, cudaFuncAttributeMaxDynamicSharedMemorySize, SMEM_TOTAL);
    dim3 grid(SQn / 128, 32);
    attn_kernel<<<grid, 256, SMEM_TOTAL>>>(Q, M, O);
}

// round 13
// speedup vs baseline: 1.1868x; 1.1868x over previous
#include <cuda_runtime.h>
#include <cuda_bf16.h>
#include <cstdint>

namespace {

constexpr int SQn = 2048, SKn = 2048, Dn = 128;
constexpr float SCALE = 22.62741699796952f; // 2*sqrt(128)

constexpr int STRIDE_W = 68;             // words per padded row (128 bf16 + 16B pad)
constexpr int STRIDE_B = STRIDE_W * 4;   // 272 B
constexpr int HALF_B   = 32 * STRIDE_B;  // 8704 B (32 rows, hi or lo)
constexpr int KSTG_B   = 2 * HALF_B;     // 17408 B per stage (hi+lo)
constexpr int SV_OFF   = 4 * KSTG_B;     // 69632  (V stages after 4 K stages)
constexpr int SP_OFF   = 2 * SV_OFF;     // 139264 (P buffers)
constexpr int SMEM_TOTAL = SP_OFF + 4 * 4096;  // 155648 B
constexpr int NITER = SKn / 32;          // 64 nc steps

// scratch (R10 layout): [bh(32)][chunk64(32)][KH,KL,VH,VL (17408 B each)]
constexpr int NCH64   = 32;
constexpr int BUF64_B = 64 * STRIDE_B;   // 17408
constexpr int SCH64_B = 4 * BUF64_B;     // 69632
__device__ __align__(16) char g_scratch[32ull * NCH64 * SCH64_B];

__device__ __forceinline__ uint32_t packbf(float a, float b) {
    __nv_bfloat162 t = __floats2bfloat162_rn(a, b);
    return *reinterpret_cast<uint32_t*>(&t);
}
__device__ __forceinline__ uint32_t prmt_hi(uint32_t a, uint32_t b) {
    uint32_t d; asm("prmt.b32 %0,%1,%2,0x7632;" : "=r"(d) : "r"(a), "r"(b)); return d;
}
__device__ __forceinline__ float truncbf(float x) {
    return __uint_as_float(__float_as_uint(x) & 0xFFFF0000u);
}
__device__ __forceinline__ void mma16816(float* d, const uint32_t* a, uint32_t b0, uint32_t b1) {
    asm volatile(
        "mma.sync.aligned.m16n8k16.row.col.f32.bf16.bf16.f32 "
        "{%0,%1,%2,%3}, {%4,%5,%6,%7}, {%8,%9}, {%0,%1,%2,%3};\n"
        : "+f"(d[0]), "+f"(d[1]), "+f"(d[2]), "+f"(d[3])
        : "r"(a[0]), "r"(a[1]), "r"(a[2]), "r"(a[3]), "r"(b0), "r"(b1));
}
__device__ __forceinline__ void ldsm4(uint32_t* r, uint32_t saddr) {
    asm volatile("ldmatrix.sync.aligned.m8n8.x4.shared.b16 {%0,%1,%2,%3}, [%4];\n"
                 : "=r"(r[0]), "=r"(r[1]), "=r"(r[2]), "=r"(r[3]) : "r"(saddr));
}
__device__ __forceinline__ void ldsm4t(uint32_t* r, uint32_t saddr) {
    asm volatile("ldmatrix.sync.aligned.m8n8.x4.trans.shared.b16 {%0,%1,%2,%3}, [%4];\n"
                 : "=r"(r[0]), "=r"(r[1]), "=r"(r[2]), "=r"(r[3]) : "r"(saddr));
}
__device__ __forceinline__ void stsm4(uint32_t saddr, const uint32_t* r) {
    asm volatile("stmatrix.sync.aligned.m8n8.x4.shared.b16 [%0], {%1,%2,%3,%4};\n"
                 :: "r"(saddr), "r"(r[0]), "r"(r[1]), "r"(r[2]), "r"(r[3]) : "memory");
}
__device__ __forceinline__ void cp16(uint32_t sdst, const void* gsrc) {
    asm volatile("cp.async.cg.shared.global [%0], [%1], 16;" :: "r"(sdst), "l"(gsrc) : "memory");
}
#define CP_COMMIT() asm volatile("cp.async.commit_group;" ::: "memory")
#define CP_WAIT(n)  asm volatile("cp.async.wait_group %0;" :: "n"(n) : "memory")

__device__ __forceinline__ void bar_sync128(int id) {
    asm volatile("bar.sync %0, 128;" :: "r"(id) : "memory");
}
__device__ __forceinline__ void bar_sync64(int id) {
    asm volatile("bar.sync %0, 64;" :: "r"(id) : "memory");
}
__device__ __forceinline__ void bar_arrive64(int id) {
    asm volatile("bar.arrive %0, 64;" :: "r"(id) : "memory");
}

// ---------------- pre-pass: K,V fp32 -> hi/lo bf16 scratch (padded rows) ----------------
__global__ __launch_bounds__(256) void prepass(const float* __restrict__ K,
                                               const float* __restrict__ V) {
    uint32_t g = blockIdx.x * 256u + threadIdx.x;   // 0 .. 4194303
    int c4 = g & 31;                 // float4 within row
    int r  = (g >> 5) & 2047;        // key row
    int bh = (g >> 16) & 31;
    int tv = g >> 21;                // 0 = K, 1 = V
    const float* src = (tv ? V : K) + (((size_t)bh * SKn + r) * Dn + c4 * 4);
    float4 f = *reinterpret_cast<const float4*>(src);
    uint32_t bx = __float_as_uint(f.x), by = __float_as_uint(f.y);
    uint32_t bz = __float_as_uint(f.z), bw = __float_as_uint(f.w);
    uint2 hi = make_uint2(prmt_hi(bx, by), prmt_hi(bz, bw));
    uint2 lo = make_uint2(packbf(f.x - truncbf(f.x), f.y - truncbf(f.y)),
                          packbf(f.z - truncbf(f.z), f.w - truncbf(f.w)));
    char* base = g_scratch
        + (((size_t)bh * NCH64 + (r >> 6)) * 4 + (tv ? 2 : 0)) * (size_t)BUF64_B
        + (r & 63) * STRIDE_B + c4 * 8;
    *reinterpret_cast<uint2*>(base)           = hi;
    *reinterpret_cast<uint2*>(base + BUF64_B) = lo;
}

// ---------------- main kernel: warp-specialized GEMM1 / GEMM2 ping-pong ----------------
__global__ __launch_bounds__(256, 1) void attn_kernel(
    const float* __restrict__ Q, const int* __restrict__ M, float* __restrict__ O)
{
    extern __shared__ char smem[];
    const uint32_t sb = (uint32_t)__cvta_generic_to_shared(smem);

    // Q (hi/lo) transiently overlays the K stages: 2 x 128 x 272 = 69632 B
    uint32_t* Qh = reinterpret_cast<uint32_t*>(smem);
    uint32_t* Ql = reinterpret_cast<uint32_t*>(smem + 128 * STRIDE_B);
    const uint32_t sQh = sb, sQl = sb + 128 * STRIDE_B;

    const int tid  = threadIdx.x;
    const int warp = tid >> 5, lane = tid & 31;
    const int gid  = lane >> 2, qid = lane & 3;
    const int pw   = warp & 3;            // pair index (S-warp pw <-> O-warp pw)

    const int bh = blockIdx.y;
    const int qt = blockIdx.x;

    const float* Qg = Q + ((size_t)bh * SQn + (size_t)qt * 128) * Dn;
    const int*   Mg = M + ((size_t)bh * SQn + (size_t)qt * 128) * SKn;
    float*       Og = O + ((size_t)bh * SQn + (size_t)qt * 128) * Dn;
    const char*  Sg = g_scratch + (size_t)bh * NCH64 * SCH64_B;

    // lane-derived ldmatrix offsets (bytes)
    const uint32_t bkOff = ((lane & 7) + ((lane >> 4) & 1) * 8) * STRIDE_B + ((lane >> 3) & 1) * 16;
    const uint32_t vOff  = ((lane & 7) + ((lane >> 3) & 1) * 8) * STRIDE_B + ((lane >> 4) & 1) * 16;

    // ---- Q tile: global -> smem (hi/lo), all 256 threads ----
    {
        const float4* src = reinterpret_cast<const float4*>(Qg);
        #pragma unroll
        for (int it = 0; it < 16; ++it) {
            int idx = tid + it * 256;
            int row = idx >> 5, c4 = idx & 31;
            float4 v = src[idx];
            uint32_t bx = __float_as_uint(v.x), by = __float_as_uint(v.y);
            uint32_t bz = __float_as_uint(v.z), bw = __float_as_uint(v.w);
            int off = row * STRIDE_W + c4 * 2;
            *reinterpret_cast<uint2*>(Qh + off) = make_uint2(prmt_hi(bx, by), prmt_hi(bz, bw));
            *reinterpret_cast<uint2*>(Ql + off) =
                make_uint2(packbf(v.x - truncbf(v.x), v.y - truncbf(v.y)),
                           packbf(v.z - truncbf(v.z), v.w - truncbf(v.w)));
        }
    }
    __syncthreads();

    // ---- hoist Q fragments for rows [32*pw, 32*pw+32) (all warps; only S-path uses) ----
    uint32_t qfh[2][8][4], qfl[2][8][4];
    #pragma unroll
    for (int mt = 0; mt < 2; ++mt) {
        const uint32_t qo = (uint32_t)(32 * pw + 16 * mt + (lane & 15)) * STRIDE_B
                          + ((lane >> 4) & 1) * 16;
        #pragma unroll
        for (int ds = 0; ds < 8; ++ds) {
            ldsm4(qfh[mt][ds], sQh + qo + ds * 32);
            ldsm4(qfl[mt][ds], sQl + qo + ds * 32);
        }
    }
    __syncthreads();   // Q reads done before K stages are overwritten

    if (warp < 4) {
        // ================= S-warps: GEMM1 producer =================
        // prologue: K stages 0..2
        #pragma unroll
        for (int n = 0; n < 3; ++n) {
            const char* srcH = Sg + (size_t)(n >> 1) * SCH64_B + (n & 1) * HALF_B;
            const uint32_t dstH = sb + (n & 3) * KSTG_B;
            #pragma unroll
            for (int i = 0; i < 5; ++i) {
                int idx = i * 128 + tid;
                if (idx < 544) {
                    cp16(dstH + idx * 16,          srcH + idx * 16);
                    cp16(dstH + HALF_B + idx * 16, srcH + BUF64_B + idx * 16);
                }
            }
            CP_COMMIT();
        }

        #pragma unroll 1
        for (int nc = 0; nc < NITER; ++nc) {
            CP_WAIT(2);
            bar_sync128(9);                       // K[nc] visible to all S-warps

            const uint32_t sKH = sb + (nc & 3) * KSTG_B;
            const uint32_t sKL = sKH + HALF_B;

            // mask prefetch: rows 32pw+16mt+gid(+8), cols nc*32 + qid*2 + 8j
            int2 ma[2][4], mb[2][4];
            #pragma unroll
            for (int mt = 0; mt < 2; ++mt) {
                const int* m0 = Mg + (size_t)(32 * pw + 16 * mt + gid) * SKn + nc * 32 + qid * 2;
                const int* m1 = m0 + 8 * (size_t)SKn;
                #pragma unroll
                for (int j = 0; j < 4; ++j) {
                    ma[mt][j] = *reinterpret_cast<const int2*>(m0 + j * 8);
                    mb[mt][j] = *reinterpret_cast<const int2*>(m1 + j * 8);
                }
            }

            // GEMM1: S[32 rows x 32 keys], K frags shared across both m-tiles
            float s[2][4][4];
            #pragma unroll
            for (int mt = 0; mt < 2; ++mt)
                #pragma unroll
                for (int j = 0; j < 4; ++j)
                    { s[mt][j][0]=0.f; s[mt][j][1]=0.f; s[mt][j][2]=0.f; s[mt][j][3]=0.f; }

            #pragma unroll
            for (int ds = 0; ds < 8; ++ds) {
                uint32_t bh0[4], bh1[4], bl0[4], bl1[4];
                const uint32_t kcol = bkOff + ds * 32;
                ldsm4(bh0, sKH + kcol);
                ldsm4(bh1, sKH + 16 * STRIDE_B + kcol);
                ldsm4(bl0, sKL + kcol);
                ldsm4(bl1, sKL + 16 * STRIDE_B + kcol);
                #pragma unroll
                for (int mt = 0; mt < 2; ++mt) {
                    mma16816(s[mt][0], qfh[mt][ds], bh0[0], bh0[1]);
                    mma16816(s[mt][1], qfh[mt][ds], bh0[2], bh0[3]);
                    mma16816(s[mt][2], qfh[mt][ds], bh1[0], bh1[1]);
                    mma16816(s[mt][3], qfh[mt][ds], bh1[2], bh1[3]);
                    mma16816(s[mt][0], qfl[mt][ds], bh0[0], bh0[1]);
                    mma16816(s[mt][1], qfl[mt][ds], bh0[2], bh0[3]);
                    mma16816(s[mt][2], qfl[mt][ds], bh1[0], bh1[1]);
                    mma16816(s[mt][3], qfl[mt][ds], bh1[2], bh1[3]);
                    mma16816(s[mt][0], qfh[mt][ds], bl0[0], bl0[1]);
                    mma16816(s[mt][1], qfh[mt][ds], bl0[2], bl0[3]);
                    mma16816(s[mt][2], qfh[mt][ds], bl1[0], bl1[1]);
                    mma16816(s[mt][3], qfh[mt][ds], bl1[2], bl1[3]);
                }
            }

            if (nc) bar_sync64(5 + pw);           // empty: O consumed P(nc-1)

            // mask + scale -> pack -> stmatrix P (A-fragment layout)
            const uint32_t PB = sb + SP_OFF + pw * 4096 + lane * 16;
            #pragma unroll
            for (int mt = 0; mt < 2; ++mt) {
                float p[4][4];
                #pragma unroll
                for (int j = 0; j < 4; ++j) {
                    p[j][0] = ma[mt][j].x ? s[mt][j][0] * SCALE : 0.f;
                    p[j][1] = ma[mt][j].y ? s[mt][j][1] * SCALE : 0.f;
                    p[j][2] = mb[mt][j].x ? s[mt][j][2] * SCALE : 0.f;
                    p[j][3] = mb[mt][j].y ? s[mt][j][3] * SCALE : 0.f;
                }
                #pragma unroll
                for (int kk = 0; kk < 2; ++kk) {
                    const float* p0 = p[kk*2 + 0];
                    const float* p1 = p[kk*2 + 1];
                    uint32_t ahi[4], alo[4];
                    ahi[0] = prmt_hi(__float_as_uint(p0[0]), __float_as_uint(p0[1]));
                    ahi[1] = prmt_hi(__float_as_uint(p0[2]), __float_as_uint(p0[3]));
                    ahi[2] = prmt_hi(__float_as_uint(p1[0]), __float_as_uint(p1[1]));
                    ahi[3] = prmt_hi(__float_as_uint(p1[2]), __float_as_uint(p1[3]));
                    alo[0] = packbf(p0[0] - truncbf(p0[0]), p0[1] - truncbf(p0[1]));
                    alo[1] = packbf(p0[2] - truncbf(p0[2]), p0[3] - truncbf(p0[3]));
                    alo[2] = packbf(p1[0] - truncbf(p1[0]), p1[1] - truncbf(p1[1]));
                    alo[3] = packbf(p1[2] - truncbf(p1[2]), p1[3] - truncbf(p1[3]));
                    stsm4(PB + (mt * 2 + kk) * 512,        ahi);
                    stsm4(PB + 2048 + (mt * 2 + kk) * 512, alo);
                }
            }
            bar_arrive64(1 + pw);                 // full: P(nc) ready

            // refill K[nc+3]
            const int n = nc + 3;
            if (n < NITER) {
                const char* srcH = Sg + (size_t)(n >> 1) * SCH64_B + (n & 1) * HALF_B;
                const uint32_t dstH = sb + (n & 3) * KSTG_B;
                #pragma unroll
                for (int i = 0; i < 5; ++i) {
                    int idx = i * 128 + tid;
                    if (idx < 544) {
                        cp16(dstH + idx * 16,          srcH + idx * 16);
                        cp16(dstH + HALF_B + idx * 16, srcH + BUF64_B + idx * 16);
                    }
                }
            }
            CP_COMMIT();
        }
    } else {
        // ================= O-warps: GEMM2 consumer =================
        const int tid2 = tid - 128;

        // prologue: V stages 0..2
        #pragma unroll
        for (int n = 0; n < 3; ++n) {
            const char* srcH = Sg + (size_t)(n >> 1) * SCH64_B + 2 * BUF64_B + (n & 1) * HALF_B;
            const uint32_t dstH = sb + SV_OFF + (n & 3) * KSTG_B;
            #pragma unroll
            for (int i = 0; i < 5; ++i) {
                int idx = i * 128 + tid2;
                if (idx < 544) {
                    cp16(dstH + idx * 16,          srcH + idx * 16);
                    cp16(dstH + HALF_B + idx * 16, srcH + BUF64_B + idx * 16);
                }
            }
            CP_COMMIT();
        }

        float o[2][16][4];
        #pragma unroll
        for (int mt = 0; mt < 2; ++mt)
            #pragma unroll
            for (int i = 0; i < 16; ++i)
                { o[mt][i][0]=0.f; o[mt][i][1]=0.f; o[mt][i][2]=0.f; o[mt][i][3]=0.f; }

        #pragma unroll 1
        for (int nc = 0; nc < NITER; ++nc) {
            CP_WAIT(2);
            bar_sync128(10);                      // V[nc] visible to all O-warps

            const uint32_t sVH = sb + SV_OFF + (nc & 3) * KSTG_B;
            const uint32_t sVL = sVH + HALF_B;

            bar_sync64(1 + pw);                   // full: P(nc) ready
            uint32_t ah[2][2][4], al[2][2][4];
            const uint32_t PB = sb + SP_OFF + pw * 4096 + lane * 16;
            #pragma unroll
            for (int mt = 0; mt < 2; ++mt)
                #pragma unroll
                for (int kk = 0; kk < 2; ++kk) {
                    ldsm4(ah[mt][kk], PB + (mt * 2 + kk) * 512);
                    ldsm4(al[mt][kk], PB + 2048 + (mt * 2 + kk) * 512);
                }

            #pragma unroll
            for (int kk = 0; kk < 2; ++kk) {
                const uint32_t vbase = (uint32_t)(kk * 16) * STRIDE_B + vOff;
                #pragma unroll
                for (int tp = 0; tp < 4; ++tp) {
                    uint32_t vh0[4], vl0[4], vh1[4], vl1[4];
                    ldsm4t(vh0, sVH + vbase + (2*tp    ) * 32);
                    ldsm4t(vl0, sVL + vbase + (2*tp    ) * 32);
                    ldsm4t(vh1, sVH + vbase + (2*tp + 1) * 32);
                    ldsm4t(vl1, sVL + vbase + (2*tp + 1) * 32);
                    #pragma unroll
                    for (int mt = 0; mt < 2; ++mt) {
                        float* o0 = o[mt][4*tp + 0];
                        float* o1 = o[mt][4*tp + 1];
                        float* o2 = o[mt][4*tp + 2];
                        float* o3 = o[mt][4*tp + 3];
                        mma16816(o0, ah[mt][kk], vh0[0], vh0[1]);
                        mma16816(o1, ah[mt][kk], vh0[2], vh0[3]);
                        mma16816(o2, ah[mt][kk], vh1[0], vh1[1]);
                        mma16816(o3, ah[mt][kk], vh1[2], vh1[3]);
                        mma16816(o0, al[mt][kk], vh0[0], vh0[1]);
                        mma16816(o1, al[mt][kk], vh0[2], vh0[3]);
                        mma16816(o2, al[mt][kk], vh1[0], vh1[1]);
                        mma16816(o3, al[mt][kk], vh1[2], vh1[3]);
                        mma16816(o0, ah[mt][kk], vl0[0], vl0[1]);
                        mma16816(o1, ah[mt][kk], vl0[2], vl0[3]);
                        mma16816(o2, ah[mt][kk], vl1[0], vl1[1]);
                        mma16816(o3, ah[mt][kk], vl1[2], vl1[3]);
                    }
                }
            }
            bar_arrive64(5 + pw);                 // empty: P consumed

            // refill V[nc+3]
            const int n = nc + 3;
            if (n < NITER) {
                const char* srcH = Sg + (size_t)(n >> 1) * SCH64_B + 2 * BUF64_B + (n & 1) * HALF_B;
                const uint32_t dstH = sb + SV_OFF + (n & 3) * KSTG_B;
                #pragma unroll
                for (int i = 0; i < 5; ++i) {
                    int idx = i * 128 + tid2;
                    if (idx < 544) {
                        cp16(dstH + idx * 16,          srcH + idx * 16);
                        cp16(dstH + HALF_B + idx * 16, srcH + BUF64_B + idx * 16);
                    }
                }
            }
            CP_COMMIT();
        }

        // ---- epilogue: O-warps write rows [32*pw, 32*pw+32) ----
        #pragma unroll
        for (int mt = 0; mt < 2; ++mt) {
            float* o0 = Og + (size_t)(32 * pw + 16 * mt + gid) * Dn + qid * 2;
            float* o1 = o0 + 8 * Dn;
            #pragma unroll
            for (int nd = 0; nd < 16; ++nd) {
                *reinterpret_cast<float2*>(o0 + nd * 8) = make_float2(o[mt][nd][0], o[mt][nd][1]);
                *reinterpret_cast<float2*>(o1 + nd * 8) = make_float2(o[mt][nd][2], o[mt][nd][3]);
            }
        }
    }
}

} // namespace

extern "C" void kernel_launch(void* const* d_in, const int* in_sizes, int n_in,
                              void* d_out, int out_size) {
    (void)in_sizes; (void)n_in; (void)out_size;
    const float* Q = (const float*)d_in[0];
    const float* K = (const float*)d_in[1];
    const float* V = (const float*)d_in[2];
    const int*   M = (const int*)d_in[3];
    float*       O = (float*)d_out;

    prepass<<<16384, 256>>>(K, V);

    cudaFuncSetAttribute(attn_kernel, cudaFuncAttributeMaxDynamicSharedMemorySize, SMEM_TOTAL);
    dim3 grid(SQn / 128, 32);
    attn_kernel<<<grid, 256, SMEM_TOTAL>>>(Q, M, O);
}

// round 15
// speedup vs baseline: 1.3173x; 1.1099x over previous
#include <cuda_runtime.h>
#include <cuda_bf16.h>
#include <cstdint>

namespace {

constexpr int SQn = 2048, SKn = 2048, Dn = 128;
constexpr float SCALE = 22.62741699796952f; // 2*sqrt(128)

constexpr int STRIDE_W = 68;             // words per padded smem row (128 bf16 + 16B pad)
constexpr int STRIDE_B = STRIDE_W * 4;   // 272 B
constexpr int CHUNK_ROWS = 64;
constexpr int BUF_B   = CHUNK_ROWS * STRIDE_B;  // 17408 B (one of KH,KL,VH,VL)
constexpr int STAGE_B = 4 * BUF_B;              // 69632 B per stage
constexpr int NSTAGE  = 3;
constexpr int SMEM_TOTAL = NSTAGE * STAGE_B;    // 208896 B
constexpr int NCHUNK = SKn / CHUNK_ROWS;        // 32

// scratch: [bh(32)][chunk(32)][buf: KH,KL,VH,VL][row(64) * 272B]
__device__ __align__(16) char g_scratch[32ull * NCHUNK * STAGE_B];

__device__ __forceinline__ uint32_t packbf(float a, float b) {
    __nv_bfloat162 t = __floats2bfloat162_rn(a, b);
    return *reinterpret_cast<uint32_t*>(&t);
}
__device__ __forceinline__ uint32_t prmt_hi(uint32_t a, uint32_t b) {
    uint32_t d; asm("prmt.b32 %0,%1,%2,0x7632;" : "=r"(d) : "r"(a), "r"(b)); return d;
}
__device__ __forceinline__ float truncbf(float x) {
    return __uint_as_float(__float_as_uint(x) & 0xFFFF0000u);
}
__device__ __forceinline__ void mma16816(float* d, const uint32_t* a, uint32_t b0, uint32_t b1) {
    asm volatile(
        "mma.sync.aligned.m16n8k16.row.col.f32.bf16.bf16.f32 "
        "{%0,%1,%2,%3}, {%4,%5,%6,%7}, {%8,%9}, {%0,%1,%2,%3};\n"
        : "+f"(d[0]), "+f"(d[1]), "+f"(d[2]), "+f"(d[3])
        : "r"(a[0]), "r"(a[1]), "r"(a[2]), "r"(a[3]), "r"(b0), "r"(b1));
}
__device__ __forceinline__ void ldsm4(uint32_t* r, uint32_t saddr) {
    asm volatile("ldmatrix.sync.aligned.m8n8.x4.shared.b16 {%0,%1,%2,%3}, [%4];\n"
                 : "=r"(r[0]), "=r"(r[1]), "=r"(r[2]), "=r"(r[3]) : "r"(saddr));
}
__device__ __forceinline__ void ldsm4t(uint32_t* r, uint32_t saddr) {
    asm volatile("ldmatrix.sync.aligned.m8n8.x4.trans.shared.b16 {%0,%1,%2,%3}, [%4];\n"
                 : "=r"(r[0]), "=r"(r[1]), "=r"(r[2]), "=r"(r[3]) : "r"(saddr));
}
__device__ __forceinline__ void cp16(uint32_t sdst, const void* gsrc) {
    asm volatile("cp.async.cg.shared.global [%0], [%1], 16;" :: "r"(sdst), "l"(gsrc) : "memory");
}
#define CP_COMMIT() asm volatile("cp.async.commit_group;" ::: "memory")
#define CP_WAIT(n)  asm volatile("cp.async.wait_group %0;" :: "n"(n) : "memory")

__device__ __forceinline__ void bar_syncg(int id) {
    asm volatile("bar.sync %0, 256;" :: "r"(id) : "memory");
}
__device__ __forceinline__ void bar_arriveg(int id) {
    asm volatile("bar.arrive %0, 256;" :: "r"(id) : "memory");
}

// ---------------- pre-pass: K,V fp32 -> hi/lo bf16 scratch ----------------
__global__ __launch_bounds__(256) void prepass(const float* __restrict__ K,
                                               const float* __restrict__ V) {
    uint32_t g = blockIdx.x * 256u + threadIdx.x;   // 0 .. 4194303
    int c4 = g & 31;                 // float4 within row
    int r  = (g >> 5) & 2047;        // key row
    int bh = (g >> 16) & 31;
    int tv = g >> 21;                // 0 = K, 1 = V
    const float* src = (tv ? V : K) + (((size_t)bh * SKn + r) * Dn + c4 * 4);
    float4 f = *reinterpret_cast<const float4*>(src);
    uint32_t bx = __float_as_uint(f.x), by = __float_as_uint(f.y);
    uint32_t bz = __float_as_uint(f.z), bw = __float_as_uint(f.w);
    uint2 hi = make_uint2(prmt_hi(bx, by), prmt_hi(bz, bw));
    uint2 lo = make_uint2(packbf(f.x - truncbf(f.x), f.y - truncbf(f.y)),
                          packbf(f.z - truncbf(f.z), f.w - truncbf(f.w)));
    char* base = g_scratch
        + (((size_t)bh * NCHUNK + (r >> 6)) * 4 + (tv ? 2 : 0)) * (size_t)BUF_B
        + (r & 63) * STRIDE_B + c4 * 8;
    *reinterpret_cast<uint2*>(base)         = hi;
    *reinterpret_cast<uint2*>(base + BUF_B) = lo;
}

// ---------------- main kernel ----------------
__global__ __launch_bounds__(256, 1) void attn_kernel(
    const float* __restrict__ Q, const int* __restrict__ M, float* __restrict__ O)
{
    extern __shared__ char smem[];
    const uint32_t sb = (uint32_t)__cvta_generic_to_shared(smem);

    // Q overlays stage 0+1 region transiently (dead after fragment hoist)
    uint32_t* Qh = reinterpret_cast<uint32_t*>(smem);
    uint32_t* Ql = reinterpret_cast<uint32_t*>(smem + 128 * STRIDE_B);
    const uint32_t sQh = sb, sQl = sb + 128 * STRIDE_B;

    const int tid  = threadIdx.x;
    const int warp = tid >> 5, lane = tid & 31;
    const int gid  = lane >> 2, qid = lane & 3;
    const int qr   = warp * 16;
    const int grp  = warp >> 2;   // 0: producer+lead (rows 0-63), 1: lagging (rows 64-127)

    const int bh = blockIdx.y;
    const int qt = blockIdx.x;

    const float* Qg = Q + ((size_t)bh * SQn + (size_t)qt * 128) * Dn;
    const int*   Mg = M + ((size_t)bh * SQn + (size_t)qt * 128) * SKn;
    float*       Og = O + ((size_t)bh * SQn + (size_t)qt * 128) * Dn;
    const char*  Sg = g_scratch + (size_t)bh * NCHUNK * STAGE_B;

    // lane-derived ldmatrix offsets (bytes)
    const uint32_t bkOff = ((lane & 7) + ((lane >> 4) & 1) * 8) * STRIDE_B + ((lane >> 3) & 1) * 16;
    const uint32_t vOff  = ((lane & 7) + ((lane >> 3) & 1) * 8) * STRIDE_B + ((lane >> 4) & 1) * 16;
    const uint32_t qOff  = (qr + (lane & 15)) * STRIDE_B + ((lane >> 4) & 1) * 16;

    // ---- Q tile: global -> smem (hi/lo) ----
    {
        const float4* src = reinterpret_cast<const float4*>(Qg);
        #pragma unroll
        for (int it = 0; it < 16; ++it) {
            int idx = tid + it * 256;
            int row = idx >> 5, c4 = idx & 31;
            float4 v = src[idx];
            uint32_t bx = __float_as_uint(v.x), by = __float_as_uint(v.y);
            uint32_t bz = __float_as_uint(v.z), bw = __float_as_uint(v.w);
            int off = row * STRIDE_W + c4 * 2;
            *reinterpret_cast<uint2*>(Qh + off) = make_uint2(prmt_hi(bx, by), prmt_hi(bz, bw));
            *reinterpret_cast<uint2*>(Ql + off) =
                make_uint2(packbf(v.x - truncbf(v.x), v.y - truncbf(v.y)),
                           packbf(v.z - truncbf(v.z), v.w - truncbf(v.w)));
        }
    }
    __syncthreads();

    // ---- hoist Q fragments (invariant across chunks) ----
    uint32_t qfh[8][4], qfl[8][4];
    #pragma unroll
    for (int ds = 0; ds < 8; ++ds) {
        ldsm4(qfh[ds], sQh + qOff + ds * 32);
        ldsm4(qfl[ds], sQl + qOff + ds * 32);
    }
    __syncthreads();   // Q reads done before stage 0 is overwritten

    // ---- g0 prologue: issue chunks 0,1 into stages 0,1 ----
    if (grp == 0) {
        #pragma unroll
        for (int n = 0; n < 2; ++n) {
            const char* gb = Sg + (size_t)n * STAGE_B;
            const uint32_t sn = sb + n * STAGE_B;
            #pragma unroll 4
            for (int i = 0; i < 32; ++i) {
                int idx = i * 128 + tid;              // tid < 128 for grp 0
                int buf = idx >> 10, w = idx & 1023;
                uint32_t off = buf * BUF_B + (w >> 4) * STRIDE_B + (w & 15) * 16;
                cp16(sn + off, gb + off);
            }
            CP_COMMIT();
        }
    }

    float o[16][4];
    #pragma unroll
    for (int i = 0; i < 16; ++i)
        #pragma unroll
        for (int j = 0; j < 4; ++j) o[i][j] = 0.f;

    #pragma unroll 1
    for (int c = 0; c < NCHUNK; ++c) {
        const int st_i = c - (c / NSTAGE) * NSTAGE;     // c % 3

        // ---- acquire chunk c ----
        if (grp == 0) {
            CP_WAIT(1);          // pending <= {c+1}; chunk c complete
        } else {
            bar_syncg(1 + st_i); // g0 finished computing c
        }

        const uint32_t st = sb + st_i * STAGE_B;
        const uint32_t sKH = st, sKL = st + BUF_B, sVH = st + 2 * BUF_B, sVL = st + 3 * BUF_B;
        const int koff = c * CHUNK_ROWS;

        #pragma unroll
        for (int nc = 0; nc < 2; ++nc) {
            const int kb = nc * 32;

            // mask prefetch (consumed after GEMM1)
            const int* m0 = Mg + (size_t)(qr + gid) * SKn + koff + kb + qid * 2;
            const int* m1 = m0 + 8 * (size_t)SKn;
            int2 ma[4], mb[4];
            #pragma unroll
            for (int j = 0; j < 4; ++j) {
                ma[j] = *reinterpret_cast<const int2*>(m0 + j * 8);
                mb[j] = *reinterpret_cast<const int2*>(m1 + j * 8);
            }

            // ---- GEMM1: S[16q x 32k] = Q·K^T (bf16x3), depth-1 K-frag prefetch ----
            float s[4][4];
            #pragma unroll
            for (int j = 0; j < 4; ++j) { s[j][0]=0.f; s[j][1]=0.f; s[j][2]=0.f; s[j][3]=0.f; }

            uint32_t kf[2][4][4];   // [buf][bh0,bh1,bl0,bl1][4]
            {
                const uint32_t kcol = bkOff;
                ldsm4(kf[0][0], sKH + (uint32_t)(kb     ) * STRIDE_B + kcol);
                ldsm4(kf[0][1], sKH + (uint32_t)(kb + 16) * STRIDE_B + kcol);
                ldsm4(kf[0][2], sKL + (uint32_t)(kb     ) * STRIDE_B + kcol);
                ldsm4(kf[0][3], sKL + (uint32_t)(kb + 16) * STRIDE_B + kcol);
            }
            #pragma unroll
            for (int ds = 0; ds < 8; ++ds) {
                uint32_t (*cur)[4] = kf[ds & 1];
                if (ds < 7) {
                    uint32_t (*nxt)[4] = kf[(ds + 1) & 1];
                    const uint32_t kcol = bkOff + (ds + 1) * 32;
                    ldsm4(nxt[0], sKH + (uint32_t)(kb     ) * STRIDE_B + kcol);
                    ldsm4(nxt[1], sKH + (uint32_t)(kb + 16) * STRIDE_B + kcol);
                    ldsm4(nxt[2], sKL + (uint32_t)(kb     ) * STRIDE_B + kcol);
                    ldsm4(nxt[3], sKL + (uint32_t)(kb + 16) * STRIDE_B + kcol);
                }
                mma16816(s[0], qfh[ds], cur[0][0], cur[0][1]);
                mma16816(s[1], qfh[ds], cur[0][2], cur[0][3]);
                mma16816(s[2], qfh[ds], cur[1][0], cur[1][1]);
                mma16816(s[3], qfh[ds], cur[1][2], cur[1][3]);
                mma16816(s[0], qfl[ds], cur[0][0], cur[0][1]);
                mma16816(s[1], qfl[ds], cur[0][2], cur[0][3]);
                mma16816(s[2], qfl[ds], cur[1][0], cur[1][1]);
                mma16816(s[3], qfl[ds], cur[1][2], cur[1][3]);
                mma16816(s[0], qfh[ds], cur[2][0], cur[2][1]);
                mma16816(s[1], qfh[ds], cur[2][2], cur[2][3]);
                mma16816(s[2], qfh[ds], cur[3][0], cur[3][1]);
                mma16816(s[3], qfh[ds], cur[3][2], cur[3][3]);
            }

            // ---- mask + scale -> P ----
            float p[4][4];
            #pragma unroll
            for (int j = 0; j < 4; ++j) {
                p[j][0] = ma[j].x ? s[j][0] * SCALE : 0.f;
                p[j][1] = ma[j].y ? s[j][1] * SCALE : 0.f;
                p[j][2] = mb[j].x ? s[j][2] * SCALE : 0.f;
                p[j][3] = mb[j].y ? s[j][3] * SCALE : 0.f;
            }

            // ---- GEMM2: O += P[16x32]·V[32x128]; both kk packed upfront,
            //      flattened (kk,tp) steps with depth-1 V-frag prefetch.
            //      Per-accumulator MMA order identical to R10 (bit-exact). ----
            uint32_t ahi[2][4], alo[2][4];
            #pragma unroll
            for (int kk = 0; kk < 2; ++kk) {
                const float* p0 = p[kk*2 + 0];
                const float* p1 = p[kk*2 + 1];
                ahi[kk][0] = prmt_hi(__float_as_uint(p0[0]), __float_as_uint(p0[1]));
                ahi[kk][1] = prmt_hi(__float_as_uint(p0[2]), __float_as_uint(p0[3]));
                ahi[kk][2] = prmt_hi(__float_as_uint(p1[0]), __float_as_uint(p1[1]));
                ahi[kk][3] = prmt_hi(__float_as_uint(p1[2]), __float_as_uint(p1[3]));
                alo[kk][0] = packbf(p0[0] - truncbf(p0[0]), p0[1] - truncbf(p0[1]));
                alo[kk][1] = packbf(p0[2] - truncbf(p0[2]), p0[3] - truncbf(p0[3]));
                alo[kk][2] = packbf(p1[0] - truncbf(p1[0]), p1[1] - truncbf(p1[1]));
                alo[kk][3] = packbf(p1[2] - truncbf(p1[2]), p1[3] - truncbf(p1[3]));
            }
            const uint32_t vb0 = (uint32_t)(kb     ) * STRIDE_B + vOff;
            const uint32_t vb1 = (uint32_t)(kb + 16) * STRIDE_B + vOff;

            uint32_t fV[2][4][4];   // [buf][vh0,vl0,vh1,vl1][4]
            {
                ldsm4t(fV[0][0], sVH + vb0);
                ldsm4t(fV[0][1], sVL + vb0);
                ldsm4t(fV[0][2], sVH + vb0 + 32);
                ldsm4t(fV[0][3], sVL + vb0 + 32);
            }
            #pragma unroll
            for (int sstep = 0; sstep < 8; ++sstep) {
                const int kk = sstep & 1;       // step order: (kk0,tp0),(kk1,tp0),(kk0,tp1)...
                const int tp = sstep >> 1;
                uint32_t (*cv)[4] = fV[sstep & 1];
                if (sstep < 7) {
                    const int nkk = (sstep + 1) & 1;
                    const int ntp = (sstep + 1) >> 1;
                    const uint32_t base = (nkk ? vb1 : vb0) + (uint32_t)ntp * 64;
                    uint32_t (*nv)[4] = fV[(sstep + 1) & 1];
                    ldsm4t(nv[0], sVH + base);
                    ldsm4t(nv[1], sVL + base);
                    ldsm4t(nv[2], sVH + base + 32);
                    ldsm4t(nv[3], sVL + base + 32);
                }
                float* o0 = o[4*tp + 0];
                float* o1 = o[4*tp + 1];
                float* o2 = o[4*tp + 2];
                float* o3 = o[4*tp + 3];
                mma16816(o0, ahi[kk], cv[0][0], cv[0][1]);
                mma16816(o1, ahi[kk], cv[0][2], cv[0][3]);
                mma16816(o2, ahi[kk], cv[2][0], cv[2][1]);
                mma16816(o3, ahi[kk], cv[2][2], cv[2][3]);
                mma16816(o0, alo[kk], cv[0][0], cv[0][1]);
                mma16816(o1, alo[kk], cv[0][2], cv[0][3]);
                mma16816(o2, alo[kk], cv[2][0], cv[2][1]);
                mma16816(o3, alo[kk], cv[2][2], cv[2][3]);
                mma16816(o0, ahi[kk], cv[1][0], cv[1][1]);
                mma16816(o1, ahi[kk], cv[1][2], cv[1][3]);
                mma16816(o2, ahi[kk], cv[3][0], cv[3][1]);
                mma16816(o3, ahi[kk], cv[3][2], cv[3][3]);
            }
        }

        // ---- release / refill ----
        if (grp == 0) {
            bar_arriveg(1 + st_i);                     // full: g1 may start chunk c
            const int n = c + 2;
            if (n < NCHUNK) {
                const int sn_i = n - (n / NSTAGE) * NSTAGE;
                if (c >= 1) bar_syncg(4 + sn_i);       // empty: g1 finished chunk c-1
                const char* gb = Sg + (size_t)n * STAGE_B;
                const uint32_t sn = sb + sn_i * STAGE_B;
                #pragma unroll 4
                for (int i = 0; i < 32; ++i) {
                    int idx = i * 128 + tid;
                    int buf = idx >> 10, w = idx & 1023;
                    uint32_t off = buf * BUF_B + (w >> 4) * STRIDE_B + (w & 15) * 16;
                    cp16(sn + off, gb + off);
                }
            }
            CP_COMMIT();   // always commit (possibly empty group) to keep counts uniform
        } else {
            bar_arriveg(4 + st_i);                     // empty: g1 done with chunk c
        }
    }

    // ---- epilogue ----
    float* o0 = Og + (size_t)(qr + gid) * Dn + qid * 2;
    float* o1 = o0 + 8 * Dn;
    #pragma unroll
    for (int nd = 0; nd < 16; ++nd) {
        *reinterpret_cast<float2*>(o0 + nd * 8) = make_float2(o[nd][0], o[nd][1]);
        *reinterpret_cast<float2*>(o1 + nd * 8) = make_float2(o[nd][2], o[nd][3]);
    }
}

} // namespace

extern "C" void kernel_launch(void* const* d_in, const int* in_sizes, int n_in,
                              void* d_out, int out_size) {
    (void)in_sizes; (void)n_in; (void)out_size;
    const float* Q = (const float*)d_in[0];
    const float* K = (const float*)d_in[1];
    const float* V = (const float*)d_in[2];
    const int*   M = (const int*)d_in[3];
    float*       O = (float*)d_out;

    prepass<<<16384, 256>>>(K, V);

    cudaFuncSetAttribute(attn_kernel, cudaFuncAttributeMaxDynamicSharedMemorySize, SMEM_TOTAL);
    dim3 grid(SQn / 128, 32);
    attn_kernel<<<grid, 256, SMEM_TOTAL>>>(Q, M, O);
}